// round 5
// baseline (speedup 1.0000x reference)
#include <cuda_runtime.h>
#include <cstdint>

// Problem constants
#define B      128
#define CMAX   1024
#define DIN    1024
#define KTOT   2048          // 2 * DIN (complement coding)
#define NC     10
#define ALPHA  1e-3f
#define GAMMA  1e-2f

// choice kernel tiling
#define CT     8             // categories per block -> grid 128
#define KSLICE 128           // k per warp (16 warps cover 2048)
#define NITER  32            // KSLICE / 4

// -------- scratch (device globals; no allocation allowed) --------
__device__ float g_codedT[(KTOT + 4) * B];        // transposed [k][b], +4 pad rows for x prefetch overrun
__device__ float g_pmn[128];
__device__ float g_pmx[128];
__device__ float g_bins[B * 16];                  // per-b per-label sums (pad 16)
__device__ unsigned long long g_best[B];          // packed (value_bits<<32)|~c

// ---------------- 1. per-block min/max partials + scratch init ----------------
__global__ void mm_part_kernel(const float* __restrict__ x) {
    int tid = threadIdx.x;                       // 256 threads
    // zero the atomic scratch for this graph replay (block b owns row b)
    if (tid < 16) g_bins[blockIdx.x * 16 + tid] = 0.f;
    if (tid == 16) g_best[blockIdx.x] = 0ull;

    const float* p = x + blockIdx.x * 1024;      // 128 blocks * 1024 elems
    float mn = 3.402823466e38f, mx = -3.402823466e38f;
#pragma unroll
    for (int i = 0; i < 4; i++) {
        float v = p[tid + i * 256];
        mn = fminf(mn, v);
        mx = fmaxf(mx, v);
    }
#pragma unroll
    for (int o = 16; o; o >>= 1) {
        mn = fminf(mn, __shfl_xor_sync(0xffffffffu, mn, o));
        mx = fmaxf(mx, __shfl_xor_sync(0xffffffffu, mx, o));
    }
    __shared__ float smn[8], smx[8];
    if ((tid & 31) == 0) { smn[tid >> 5] = mn; smx[tid >> 5] = mx; }
    __syncthreads();
    if (tid == 0) {
        mn = smn[0]; mx = smx[0];
#pragma unroll
        for (int w = 1; w < 8; w++) { mn = fminf(mn, smn[w]); mx = fmaxf(mx, smx[w]); }
        g_pmn[blockIdx.x] = mn;
        g_pmx[blockIdx.x] = mx;
    }
}

// ---------------- 2. normalize + complement-code + transpose ----------------
__global__ void codedT_kernel(const float* __restrict__ x) {
    __shared__ float sT[16][129];
    __shared__ float rmn[8], rmx[8];
    __shared__ float s_mn, s_inv;
    int tid = threadIdx.x;                       // 256 threads

    {
        float mn = 3.402823466e38f, mx = -3.402823466e38f;
        if (tid < 128) { mn = g_pmn[tid]; mx = g_pmx[tid]; }
#pragma unroll
        for (int o = 16; o; o >>= 1) {
            mn = fminf(mn, __shfl_xor_sync(0xffffffffu, mn, o));
            mx = fmaxf(mx, __shfl_xor_sync(0xffffffffu, mx, o));
        }
        if ((tid & 31) == 0) { rmn[tid >> 5] = mn; rmx[tid >> 5] = mx; }
    }
    int d0 = blockIdx.x * 16;
#pragma unroll
    for (int p = 0; p < 8; p++) {
        int idx = tid + p * 256;                 // 0..2047
        int b = idx >> 4, dd = idx & 15;
        sT[dd][b] = x[b * 1024 + d0 + dd];
    }
    __syncthreads();
    if (tid == 0) {
        float mn = fminf(fminf(rmn[0], rmn[1]), fminf(rmn[2], rmn[3]));
        float mx = fmaxf(fmaxf(rmx[0], rmx[1]), fmaxf(rmx[2], rmx[3]));
        s_mn = mn;
        s_inv = 1.0f / (mx - mn + 1e-10f);
    }
    __syncthreads();
    float mn = s_mn, inv = s_inv;
#pragma unroll
    for (int p = 0; p < 8; p++) {
        int q = tid + p * 256;
        int dd = q >> 7, b = q & 127;
        float v = (sT[dd][b] - mn) * inv;
        g_codedT[(d0 + dd) * 128 + b] = v;
        g_codedT[(1024 + d0 + dd) * 128 + b] = 1.0f - v;
    }
}

// ---------------- 3. choice + fused denominator + fused argmax/label-sums ----------------
#define CP_ASYNC16(dst_u32, src_ptr) \
    asm volatile("cp.async.ca.shared.global [%0], [%1], 16;" \
                 :: "r"(dst_u32), "l"(src_ptr) : "memory")
#define CP_COMMIT()  asm volatile("cp.async.commit_group;" ::: "memory")
#define CP_WAIT2()   asm volatile("cp.async.wait_group 2;" ::: "memory")

#define MATH_BODY(XX, TST)                                                                 \
    _Pragma("unroll")                                                                      \
    for (int s = 0; s < 8; s++) {                                                          \
        float4 tf = (TST)[s];                                                              \
        float a0 = fminf(XX[0].x, tf.x), a1 = fminf(XX[1].x, tf.y);                        \
        float a2 = fminf(XX[2].x, tf.z), a3 = fminf(XX[3].x, tf.w);                        \
        acc[0][s] += (a0 + a1) + (a2 + a3);                                                \
        float b0 = fminf(XX[0].y, tf.x), b1 = fminf(XX[1].y, tf.y);                        \
        float b2 = fminf(XX[2].y, tf.z), b3 = fminf(XX[3].y, tf.w);                        \
        acc[1][s] += (b0 + b1) + (b2 + b3);                                                \
        float c0 = fminf(XX[0].z, tf.x), c1 = fminf(XX[1].z, tf.y);                        \
        float c2 = fminf(XX[2].z, tf.z), c3 = fminf(XX[3].z, tf.w);                        \
        acc[2][s] += (c0 + c1) + (c2 + c3);                                                \
        float e0 = fminf(XX[0].w, tf.x), e1 = fminf(XX[1].w, tf.y);                        \
        float e2 = fminf(XX[2].w, tf.z), e3 = fminf(XX[3].w, tf.w);                        \
        acc[3][s] += (e0 + e1) + (e2 + e3);                                                \
        ulonglong2 tu = ((const ulonglong2*)(TST))[s];                                     \
        asm volatile("add.rn.f32x2 %0, %0, %1;" : "+l"(ts2[s]) : "l"(tu.x));               \
        asm volatile("add.rn.f32x2 %0, %0, %1;" : "+l"(ts2[s]) : "l"(tu.y));               \
    }

__global__ __launch_bounds__(512)
void choice_kernel(const float* __restrict__ templates,
                   const int* __restrict__ counts,
                   const int* __restrict__ committed,
                   const int* __restrict__ labels) {
    __shared__ __align__(16) float stg[16 * 128];      // 8 KB: per-warp 4-stage ring
    __shared__ float sacc[8][128][9];                  // 36.9 KB (stride-9 pad)
    __shared__ float stsum[16][8];
    __shared__ float sden[8];
    __shared__ int   s_lab[8], s_com[8];

    int tid = threadIdx.x, w = tid >> 5, l = tid & 31;
    int cbase = blockIdx.x * CT;
    int kbase = w * KSLICE;

    if (tid < 8) { s_lab[tid] = labels[cbase + tid]; s_com[tid] = committed[cbase + tid]; }

    float* mystg = stg + w * 128;                 // 4 stages x 32 floats
    uint32_t stg_u32 = (uint32_t)__cvta_generic_to_shared(mystg);

    const float4* xp = (const float4*)g_codedT;   // row = 32 float4s
    const float* tl = templates + (size_t)(cbase + (l & 7)) * KTOT + kbase;

    float acc[4][8];
    unsigned long long ts2[8];
#pragma unroll
    for (int r = 0; r < 4; r++)
#pragma unroll
        for (int s = 0; s < 8; s++) acc[r][s] = 0.f;
#pragma unroll
    for (int s = 0; s < 8; s++) ts2[s] = 0ull;

    // prologue: stage t(0), t(1), t(2)
#pragma unroll
    for (int p = 0; p < 3; p++) {
        if (l < 8) CP_ASYNC16(stg_u32 + (p & 3) * 128 + l * 16, tl + p * 4);
        CP_COMMIT();
    }
    float4 x0[4], x1[4];
#pragma unroll
    for (int j = 0; j < 4; j++) x0[j] = xp[(kbase + j) * 32 + l];

#pragma unroll 1
    for (int i = 0; i < NITER; i += 2) {
        // ---- consume iter i (x0) ----
#pragma unroll
        for (int j = 0; j < 4; j++) x1[j] = xp[(kbase + 4 * (i + 1) + j) * 32 + l];
        CP_WAIT2();
        __syncwarp();
        if (l < 8 && i < NITER - 3)
            CP_ASYNC16(stg_u32 + ((i + 3) & 3) * 128 + l * 16, tl + (i + 3) * 4);
        CP_COMMIT();
        {
            const float4* tst = (const float4*)(mystg + (i & 3) * 32);
            MATH_BODY(x0, tst)
        }
        // ---- consume iter i+1 (x1) ----
#pragma unroll
        for (int j = 0; j < 4; j++) x0[j] = xp[(kbase + 4 * (i + 2) + j) * 32 + l];  // pad rows cover i=30
        CP_WAIT2();
        __syncwarp();
        if (l < 8 && i + 1 < NITER - 3)
            CP_ASYNC16(stg_u32 + ((i + 4) & 3) * 128 + l * 16, tl + (i + 4) * 4);
        CP_COMMIT();
        {
            const float4* tst = (const float4*)(mystg + ((i + 1) & 3) * 32);
            MATH_BODY(x1, tst)
        }
    }

    // ---- per-warp template sums ----
    if (l == 0) {
#pragma unroll
        for (int s = 0; s < 8; s++) {
            float lo = __uint_as_float((unsigned)(ts2[s] & 0xffffffffull));
            float hi = __uint_as_float((unsigned)(ts2[s] >> 32));
            stsum[w][s] = lo + hi;
        }
    }

    // ---- staged cross-warp (k-split) reduction: 16 warps -> 8 slices ----
    int half = w >> 1;
    if ((w & 1) == 0) {
#pragma unroll
        for (int r = 0; r < 4; r++) {
            int b = 4 * l + r;
#pragma unroll
            for (int s = 0; s < 8; s++) sacc[half][b][s] = acc[r][s];
        }
    }
    __syncthreads();
    if (w & 1) {
#pragma unroll
        for (int r = 0; r < 4; r++) {
            int b = 4 * l + r;
#pragma unroll
            for (int s = 0; s < 8; s++) sacc[half][b][s] += acc[r][s];
        }
    }
    __syncthreads();
    if (tid < 8) {
        float ssum = 0.f;
#pragma unroll
        for (int ww = 0; ww < 16; ww++) ssum += stsum[ww][tid];
        sden[tid] = ALPHA + ssum + GAMMA * (float)counts[cbase + tid];
    }
    __syncthreads();

    // ---- fused epilogue: choice -> atomics (no g_choice roundtrip) ----
    unsigned long long bestp[2];
#pragma unroll
    for (int h = 0; h < 2; h++) {
        int p = tid + h * 512;
        int b = p >> 3, s = p & 7;
        float v = 0.f;
#pragma unroll
        for (int hh = 0; hh < 8; hh++) v += sacc[hh][b][s];
        float vd = v / sden[s];
        bool com = s_com[s] != 0;
        if (com) atomicAdd(&g_bins[b * 16 + s_lab[s]], vd);
        bestp[h] = com
            ? ((unsigned long long)__float_as_uint(vd) << 32) | (unsigned)(~(cbase + s))
            : 0ull;
    }
    // per-b max over the 8 s values (8 consecutive lanes share a b)
#pragma unroll
    for (int o = 4; o; o >>= 1) {
        unsigned long long o0 = __shfl_xor_sync(0xffffffffu, bestp[0], o);
        unsigned long long o1 = __shfl_xor_sync(0xffffffffu, bestp[1], o);
        if (o0 > bestp[0]) bestp[0] = o0;
        if (o1 > bestp[1]) bestp[1] = o1;
    }
    if ((tid & 7) == 0) {
        atomicMax(&g_best[tid >> 3], bestp[0]);
        atomicMax(&g_best[64 + (tid >> 3)], bestp[1]);
    }
}

// ---------------- 4. logits ----------------
__global__ void logits_kernel(const int* __restrict__ labels,
                              float* __restrict__ out) {
    int p = blockIdx.x * 320 + threadIdx.x;      // 4 blocks x 320 = 1280 = 128 b x 10 l
    if (p >= B * NC) return;
    int b = p / NC, l = p - b * NC;
    unsigned long long packed = g_best[b];
    int idx = (int)((~(unsigned)packed) & (CMAX - 1));
    int plab = labels[idx];
    out[p] = (l == plab) ? g_bins[b * 16 + l] : 0.f;
}

// ---------------- launch ----------------
extern "C" void kernel_launch(void* const* d_in, const int* in_sizes, int n_in,
                              void* d_out, int out_size) {
    const float* x         = (const float*)d_in[0];
    const float* templates = (const float*)d_in[1];
    const int*   committed = (const int*)d_in[2];     // bool -> int32
    const int*   labels    = (const int*)d_in[3];
    const int*   counts    = (const int*)d_in[4];
    float*       out       = (float*)d_out;

    mm_part_kernel<<<128, 256>>>(x);
    codedT_kernel<<<64, 256>>>(x);
    choice_kernel<<<CMAX / CT, 512>>>(templates, counts, committed, labels);
    logits_kernel<<<4, 320>>>(labels, out);
}

// round 9
// speedup vs baseline: 1.0422x; 1.0422x over previous
#include <cuda_runtime.h>
#include <cstdint>

// Problem constants
#define B      128
#define CMAX   1024
#define DIN    1024
#define KTOT   2048          // 2 * DIN (complement coding)
#define NC     10
#define ALPHA  1e-3f
#define GAMMA  1e-2f

// choice kernel tiling
#define CT     8             // categories per block -> grid 128
#define KSLICE 128           // k per warp (16 warps cover 2048)
#define NITER  32            // KSLICE / 4

// -------- scratch (device globals; no allocation allowed) --------
__device__ float g_codedT[(KTOT + 4) * B];   // transposed [k][b], +4 pad rows for x prefetch overrun
__device__ float g_choice[B * CMAX];
__device__ float g_pmn[128];
__device__ float g_pmx[128];

// ---------------- 1. per-block min/max partials ----------------
__global__ void mm_part_kernel(const float* __restrict__ x) {
    int tid = threadIdx.x;                       // 256 threads
    const float* p = x + blockIdx.x * 1024;      // 128 blocks * 1024 elems
    float mn = 3.402823466e38f, mx = -3.402823466e38f;
#pragma unroll
    for (int i = 0; i < 4; i++) {
        float v = p[tid + i * 256];
        mn = fminf(mn, v);
        mx = fmaxf(mx, v);
    }
#pragma unroll
    for (int o = 16; o; o >>= 1) {
        mn = fminf(mn, __shfl_xor_sync(0xffffffffu, mn, o));
        mx = fmaxf(mx, __shfl_xor_sync(0xffffffffu, mx, o));
    }
    __shared__ float smn[8], smx[8];
    if ((tid & 31) == 0) { smn[tid >> 5] = mn; smx[tid >> 5] = mx; }
    __syncthreads();
    if (tid == 0) {
        mn = smn[0]; mx = smx[0];
#pragma unroll
        for (int w = 1; w < 8; w++) { mn = fminf(mn, smn[w]); mx = fmaxf(mx, smx[w]); }
        g_pmn[blockIdx.x] = mn;
        g_pmx[blockIdx.x] = mx;
    }
}

// ---------------- 2. normalize + complement-code + transpose ----------------
__global__ void codedT_kernel(const float* __restrict__ x) {
    __shared__ float sT[16][129];
    __shared__ float rmn[8], rmx[8];
    __shared__ float s_mn, s_inv;
    int tid = threadIdx.x;                       // 256 threads

    {
        float mn = 3.402823466e38f, mx = -3.402823466e38f;
        if (tid < 128) { mn = g_pmn[tid]; mx = g_pmx[tid]; }
#pragma unroll
        for (int o = 16; o; o >>= 1) {
            mn = fminf(mn, __shfl_xor_sync(0xffffffffu, mn, o));
            mx = fmaxf(mx, __shfl_xor_sync(0xffffffffu, mx, o));
        }
        if ((tid & 31) == 0) { rmn[tid >> 5] = mn; rmx[tid >> 5] = mx; }
    }
    int d0 = blockIdx.x * 16;
#pragma unroll
    for (int p = 0; p < 8; p++) {
        int idx = tid + p * 256;                 // 0..2047
        int b = idx >> 4, dd = idx & 15;
        sT[dd][b] = x[b * 1024 + d0 + dd];
    }
    __syncthreads();
    if (tid == 0) {
        float mn = fminf(fminf(rmn[0], rmn[1]), fminf(rmn[2], rmn[3]));
        float mx = fmaxf(fmaxf(rmx[0], rmx[1]), fmaxf(rmx[2], rmx[3]));
        s_mn = mn;
        s_inv = 1.0f / (mx - mn + 1e-10f);
    }
    __syncthreads();
    float mn = s_mn, inv = s_inv;
#pragma unroll
    for (int p = 0; p < 8; p++) {
        int q = tid + p * 256;
        int dd = q >> 7, b = q & 127;
        float v = (sT[dd][b] - mn) * inv;
        g_codedT[(d0 + dd) * 128 + b] = v;
        g_codedT[(1024 + d0 + dd) * 128 + b] = 1.0f - v;
    }
}

// ---------------- 3. choice matrix + fused denominator ----------------
#define CP_ASYNC16(dst_u32, src_ptr) \
    asm volatile("cp.async.ca.shared.global [%0], [%1], 16;" \
                 :: "r"(dst_u32), "l"(src_ptr) : "memory")
#define CP_COMMIT()  asm volatile("cp.async.commit_group;" ::: "memory")
#define CP_WAIT2()   asm volatile("cp.async.wait_group 2;" ::: "memory")

#define MATH_BODY(XX, TST)                                                                 \
    _Pragma("unroll")                                                                      \
    for (int s = 0; s < 8; s++) {                                                          \
        float4 tf = (TST)[s];                                                              \
        float a0 = fminf(XX[0].x, tf.x), a1 = fminf(XX[1].x, tf.y);                        \
        float a2 = fminf(XX[2].x, tf.z), a3 = fminf(XX[3].x, tf.w);                        \
        acc[0][s] += (a0 + a1) + (a2 + a3);                                                \
        float b0 = fminf(XX[0].y, tf.x), b1 = fminf(XX[1].y, tf.y);                        \
        float b2 = fminf(XX[2].y, tf.z), b3 = fminf(XX[3].y, tf.w);                        \
        acc[1][s] += (b0 + b1) + (b2 + b3);                                                \
        float c0 = fminf(XX[0].z, tf.x), c1 = fminf(XX[1].z, tf.y);                        \
        float c2 = fminf(XX[2].z, tf.z), c3 = fminf(XX[3].z, tf.w);                        \
        acc[2][s] += (c0 + c1) + (c2 + c3);                                                \
        float e0 = fminf(XX[0].w, tf.x), e1 = fminf(XX[1].w, tf.y);                        \
        float e2 = fminf(XX[2].w, tf.z), e3 = fminf(XX[3].w, tf.w);                        \
        acc[3][s] += (e0 + e1) + (e2 + e3);                                                \
        ulonglong2 tu = ((const ulonglong2*)(TST))[s];                                     \
        asm volatile("add.rn.f32x2 %0, %0, %1;" : "+l"(ts2[s]) : "l"(tu.x));               \
        asm volatile("add.rn.f32x2 %0, %0, %1;" : "+l"(ts2[s]) : "l"(tu.y));               \
    }

__global__ __launch_bounds__(512)
void choice_kernel(const float* __restrict__ templates,
                   const int* __restrict__ counts) {
    __shared__ __align__(16) float stg[16 * 128];      // 8 KB: per-warp 4-stage ring
    __shared__ float sacc[8][128][9];                  // 36.9 KB (stride-9 pad)
    __shared__ float stsum[16][8];
    __shared__ float sden[8];

    int tid = threadIdx.x, w = tid >> 5, l = tid & 31;
    int cbase = blockIdx.x * CT;
    int kbase = w * KSLICE;

    float* mystg = stg + w * 128;                 // 4 stages x 32 floats
    uint32_t stg_u32 = (uint32_t)__cvta_generic_to_shared(mystg);

    const float4* xp = (const float4*)g_codedT;   // row = 32 float4s
    const float* tl = templates + (size_t)(cbase + (l & 7)) * KTOT + kbase;

    float acc[4][8];
    unsigned long long ts2[8];
#pragma unroll
    for (int r = 0; r < 4; r++)
#pragma unroll
        for (int s = 0; s < 8; s++) acc[r][s] = 0.f;
#pragma unroll
    for (int s = 0; s < 8; s++) ts2[s] = 0ull;

    // prologue: stage t(0), t(1), t(2)
#pragma unroll
    for (int p = 0; p < 3; p++) {
        if (l < 8) CP_ASYNC16(stg_u32 + (p & 3) * 128 + l * 16, tl + p * 4);
        CP_COMMIT();
    }
    float4 x0[4], x1[4];
#pragma unroll
    for (int j = 0; j < 4; j++) x0[j] = xp[(kbase + j) * 32 + l];

#pragma unroll 1
    for (int i = 0; i < NITER; i += 2) {
        // ---- consume iter i (x0); x prefetch issued before the wait ----
#pragma unroll
        for (int j = 0; j < 4; j++) x1[j] = xp[(kbase + 4 * (i + 1) + j) * 32 + l];
        CP_WAIT2();
        __syncwarp();
        if (l < 8 && i < NITER - 3)
            CP_ASYNC16(stg_u32 + ((i + 3) & 3) * 128 + l * 16, tl + (i + 3) * 4);
        CP_COMMIT();
        {
            const float4* tst = (const float4*)(mystg + (i & 3) * 32);
            MATH_BODY(x0, tst)
        }
        // ---- consume iter i+1 (x1) ----
#pragma unroll
        for (int j = 0; j < 4; j++) x0[j] = xp[(kbase + 4 * (i + 2) + j) * 32 + l];  // pad rows cover i=30
        CP_WAIT2();
        __syncwarp();
        if (l < 8 && i + 1 < NITER - 3)
            CP_ASYNC16(stg_u32 + ((i + 4) & 3) * 128 + l * 16, tl + (i + 4) * 4);
        CP_COMMIT();
        {
            const float4* tst = (const float4*)(mystg + ((i + 1) & 3) * 32);
            MATH_BODY(x1, tst)
        }
    }

    // ---- per-warp template sums ----
    if (l == 0) {
#pragma unroll
        for (int s = 0; s < 8; s++) {
            float lo = __uint_as_float((unsigned)(ts2[s] & 0xffffffffull));
            float hi = __uint_as_float((unsigned)(ts2[s] >> 32));
            stsum[w][s] = lo + hi;
        }
    }

    // ---- staged cross-warp (k-split) reduction: 16 warps -> 8 slices -> 1 ----
    int half = w >> 1;
    if ((w & 1) == 0) {
#pragma unroll
        for (int r = 0; r < 4; r++) {
            int b = 4 * l + r;
#pragma unroll
            for (int s = 0; s < 8; s++) sacc[half][b][s] = acc[r][s];
        }
    }
    __syncthreads();
    if (w & 1) {
#pragma unroll
        for (int r = 0; r < 4; r++) {
            int b = 4 * l + r;
#pragma unroll
            for (int s = 0; s < 8; s++) sacc[half][b][s] += acc[r][s];
        }
    }
    __syncthreads();
    if (tid < 8) {
        float ssum = 0.f;
#pragma unroll
        for (int ww = 0; ww < 16; ww++) ssum += stsum[ww][tid];
        sden[tid] = ALPHA + ssum + GAMMA * (float)counts[cbase + tid];
    }
    __syncthreads();
#pragma unroll
    for (int p = tid; p < 1024; p += 512) {
        int b = p >> 3, s = p & 7;
        float v = 0.f;
#pragma unroll
        for (int hh = 0; hh < 8; hh++) v += sacc[hh][b][s];
        g_choice[b * CMAX + cbase + s] = v / sden[s];
    }
}

// ---------------- 4. argmax + label sums + logits (one block per b) ----------------
__global__ void __launch_bounds__(1024) finalize_kernel(const int* __restrict__ committed,
                                                        const int* __restrict__ labels,
                                                        float* __restrict__ out) {
    __shared__ float s_bins[32][NC];
    __shared__ unsigned long long s_best[32];
    __shared__ int s_plab;

    int b = blockIdx.x;
    int tid = threadIdx.x, w = tid >> 5;

    float v  = g_choice[b * CMAX + tid];
    bool com = committed[tid] != 0;
    int  lab = labels[tid];
    float vz = com ? v : 0.f;
    // packed argmax key: value bits high (nonneg fp32 -> monotonic), ~tid low (first-index tie-break)
    unsigned long long packed = com
        ? (((unsigned long long)__float_as_uint(v)) << 32) | (unsigned)(~tid)
        : 0ull;

    float bins[NC];
#pragma unroll
    for (int l = 0; l < NC; l++) bins[l] = (lab == l) ? vz : 0.f;

#pragma unroll
    for (int o = 16; o; o >>= 1) {
        unsigned long long op = __shfl_xor_sync(0xffffffffu, packed, o);
        if (op > packed) packed = op;
#pragma unroll
        for (int l = 0; l < NC; l++)
            bins[l] += __shfl_xor_sync(0xffffffffu, bins[l], o);
    }
    if ((tid & 31) == 0) {
        s_best[w] = packed;
#pragma unroll
        for (int l = 0; l < NC; l++) s_bins[w][l] = bins[l];
    }
    __syncthreads();

    if (tid == 0) {
        unsigned long long best = s_best[0];
#pragma unroll
        for (int ww = 1; ww < 32; ww++) if (s_best[ww] > best) best = s_best[ww];
        int idx = (int)((~(unsigned)best) & (CMAX - 1));
        s_plab = labels[idx];
    }
    __syncthreads();

    if (tid < NC) {
        float tot = 0.f;
#pragma unroll
        for (int ww = 0; ww < 32; ww++) tot += s_bins[ww][tid];
        out[b * NC + tid] = (tid == s_plab) ? tot : 0.f;
    }
}

// ---------------- launch ----------------
extern "C" void kernel_launch(void* const* d_in, const int* in_sizes, int n_in,
                              void* d_out, int out_size) {
    const float* x         = (const float*)d_in[0];
    const float* templates = (const float*)d_in[1];
    const int*   committed = (const int*)d_in[2];     // bool -> int32
    const int*   labels    = (const int*)d_in[3];
    const int*   counts    = (const int*)d_in[4];
    float*       out       = (float*)d_out;

    mm_part_kernel<<<128, 256>>>(x);
    codedT_kernel<<<64, 256>>>(x);
    choice_kernel<<<CMAX / CT, 512>>>(templates, counts);
    finalize_kernel<<<B, 1024>>>(committed, labels, out);
}